// round 1
// baseline (speedup 1.0000x reference)
#include <cuda_runtime.h>
#include <cuda_bf16.h>

// Tropical (max-plus) matmul: Y[b, j] = max_i (X[b, i] + W[j, i])
// B=512, IN=1024, OUT=1024, all fp32.
//
// Compute-bound on fma (FADD) + alu (FMNMX) pipes; data is L2-resident (8MB).
// Register-tiled: 64x64 block tile, 4x4 thread tile, BK=16, double-buffered
// smem with one __syncthreads per k-tile. Grid = 16x8 = 128 blocks (~1 wave).

#define B_DIM   512
#define IN_DIM  1024
#define OUT_DIM 1024

#define BM 64
#define BN 64
#define BK 16
#define TM 4
#define TN 4
#define NTHREADS 256
#define NTILES (IN_DIM / BK)   // 64

__global__ __launch_bounds__(NTHREADS, 1)
void tropical_mm_kernel(const float* __restrict__ X,
                        const float* __restrict__ W,
                        float* __restrict__ Y) {
    // k-major smem tiles, double buffered: 2 * (16*64 + 16*64) * 4B = 16 KB
    __shared__ float Xs[2][BK][BM];
    __shared__ float Ws[2][BK][BN];

    const int tid = threadIdx.x;
    const int tx  = tid & 15;   // 0..15 over N (cols)
    const int ty  = tid >> 4;   // 0..15 over M (rows)
    const int bm  = blockIdx.y * BM;
    const int bn  = blockIdx.x * BN;

    // Loader mapping: lr = row within tile (0..63), lc = k offset (0/4/8/12).
    // Warp lanes span 32 consecutive rows -> STS into Xs[k][lr] is
    // conflict-free (bank = lr % 32, all distinct within a warp).
    const int lr = tid & 63;
    const int lc = (tid >> 6) << 2;

    const float* Xg = X + (size_t)(bm + lr) * IN_DIM + lc;
    const float* Wg = W + (size_t)(bn + lr) * IN_DIM + lc;

    const float NEG_INF = __int_as_float(0xff800000);
    float acc[TM][TN];
#pragma unroll
    for (int i = 0; i < TM; i++)
#pragma unroll
        for (int j = 0; j < TN; j++)
            acc[i][j] = NEG_INF;

    // ---- prologue: load tile 0 into buffer 0 ----
    float4 xv = *(const float4*)(Xg);
    float4 wv = *(const float4*)(Wg);
    Xs[0][lc + 0][lr] = xv.x;
    Xs[0][lc + 1][lr] = xv.y;
    Xs[0][lc + 2][lr] = xv.z;
    Xs[0][lc + 3][lr] = xv.w;
    Ws[0][lc + 0][lr] = wv.x;
    Ws[0][lc + 1][lr] = wv.y;
    Ws[0][lc + 2][lr] = wv.z;
    Ws[0][lc + 3][lr] = wv.w;
    __syncthreads();

    int buf = 0;
    for (int kt = 1; kt < NTILES; kt++) {
        // prefetch next tile (global, L2-resident after first wave)
        xv = *(const float4*)(Xg + kt * BK);
        wv = *(const float4*)(Wg + kt * BK);

        // compute on current buffer
#pragma unroll
        for (int k = 0; k < BK; k++) {
            float4 a = *(const float4*)(&Xs[buf][k][ty * TM]);
            float4 b = *(const float4*)(&Ws[buf][k][tx * TN]);
            float xa0 = a.x, xa1 = a.y, xa2 = a.z, xa3 = a.w;
            float wb0 = b.x, wb1 = b.y, wb2 = b.z, wb3 = b.w;
            acc[0][0] = fmaxf(acc[0][0], xa0 + wb0);
            acc[0][1] = fmaxf(acc[0][1], xa0 + wb1);
            acc[0][2] = fmaxf(acc[0][2], xa0 + wb2);
            acc[0][3] = fmaxf(acc[0][3], xa0 + wb3);
            acc[1][0] = fmaxf(acc[1][0], xa1 + wb0);
            acc[1][1] = fmaxf(acc[1][1], xa1 + wb1);
            acc[1][2] = fmaxf(acc[1][2], xa1 + wb2);
            acc[1][3] = fmaxf(acc[1][3], xa1 + wb3);
            acc[2][0] = fmaxf(acc[2][0], xa2 + wb0);
            acc[2][1] = fmaxf(acc[2][1], xa2 + wb1);
            acc[2][2] = fmaxf(acc[2][2], xa2 + wb2);
            acc[2][3] = fmaxf(acc[2][3], xa2 + wb3);
            acc[3][0] = fmaxf(acc[3][0], xa3 + wb0);
            acc[3][1] = fmaxf(acc[3][1], xa3 + wb1);
            acc[3][2] = fmaxf(acc[3][2], xa3 + wb2);
            acc[3][3] = fmaxf(acc[3][3], xa3 + wb3);
        }

        // store prefetched tile into the other buffer.
        // Safe: the sync at the end of the PREVIOUS iteration guaranteed all
        // reads of buf^1 completed; this iteration only reads buf.
        buf ^= 1;
        Xs[buf][lc + 0][lr] = xv.x;
        Xs[buf][lc + 1][lr] = xv.y;
        Xs[buf][lc + 2][lr] = xv.z;
        Xs[buf][lc + 3][lr] = xv.w;
        Ws[buf][lc + 0][lr] = wv.x;
        Ws[buf][lc + 1][lr] = wv.y;
        Ws[buf][lc + 2][lr] = wv.z;
        Ws[buf][lc + 3][lr] = wv.w;
        __syncthreads();
    }

    // ---- final tile ----
#pragma unroll
    for (int k = 0; k < BK; k++) {
        float4 a = *(const float4*)(&Xs[buf][k][ty * TM]);
        float4 b = *(const float4*)(&Ws[buf][k][tx * TN]);
        float xa0 = a.x, xa1 = a.y, xa2 = a.z, xa3 = a.w;
        float wb0 = b.x, wb1 = b.y, wb2 = b.z, wb3 = b.w;
        acc[0][0] = fmaxf(acc[0][0], xa0 + wb0);
        acc[0][1] = fmaxf(acc[0][1], xa0 + wb1);
        acc[0][2] = fmaxf(acc[0][2], xa0 + wb2);
        acc[0][3] = fmaxf(acc[0][3], xa0 + wb3);
        acc[1][0] = fmaxf(acc[1][0], xa1 + wb0);
        acc[1][1] = fmaxf(acc[1][1], xa1 + wb1);
        acc[1][2] = fmaxf(acc[1][2], xa1 + wb2);
        acc[1][3] = fmaxf(acc[1][3], xa1 + wb3);
        acc[2][0] = fmaxf(acc[2][0], xa2 + wb0);
        acc[2][1] = fmaxf(acc[2][1], xa2 + wb1);
        acc[2][2] = fmaxf(acc[2][2], xa2 + wb2);
        acc[2][3] = fmaxf(acc[2][3], xa2 + wb3);
        acc[3][0] = fmaxf(acc[3][0], xa3 + wb0);
        acc[3][1] = fmaxf(acc[3][1], xa3 + wb1);
        acc[3][2] = fmaxf(acc[3][2], xa3 + wb2);
        acc[3][3] = fmaxf(acc[3][3], xa3 + wb3);
    }

    // ---- epilogue: vectorized stores (n-contiguous) ----
#pragma unroll
    for (int i = 0; i < TM; i++) {
        float4 o;
        o.x = acc[i][0];
        o.y = acc[i][1];
        o.z = acc[i][2];
        o.w = acc[i][3];
        *(float4*)(&Y[(size_t)(bm + ty * TM + i) * OUT_DIM + bn + tx * TN]) = o;
    }
}

extern "C" void kernel_launch(void* const* d_in, const int* in_sizes, int n_in,
                              void* d_out, int out_size) {
    // X: 512*1024 = 524288 elems, W: 1024*1024 = 1048576 elems.
    const float* X;
    const float* W;
    if (in_sizes[0] == B_DIM * IN_DIM) {
        X = (const float*)d_in[0];
        W = (const float*)d_in[1];
    } else {
        X = (const float*)d_in[1];
        W = (const float*)d_in[0];
    }
    float* Y = (float*)d_out;

    dim3 grid(OUT_DIM / BN, B_DIM / BM);  // 16 x 8 = 128 blocks
    dim3 block(NTHREADS);
    tropical_mm_kernel<<<grid, block>>>(X, W, Y);
}

// round 3
// speedup vs baseline: 1.0924x; 1.0924x over previous
#include <cuda_runtime.h>
#include <cuda_bf16.h>

// Tropical (max-plus) matmul: Y[b, j] = max_i (X[b, i] + W[j, i])
// B=512, IN=1024, OUT=1024, all fp32.
//
// Issue-bound on fma(FADD)+alu(FMNMX); data L2-resident. R0 showed
// issue=52% at occ=12.5% (2 warps/SMSP). This version: split-K=2 inside a
// 512-thread CTA -> 4 warps/SMSP with the same 34-instr/32-op mainloop.
// 64x64 block tile, 4x4 thread tile, BK=16, double-buffered smem per k-group.

#define B_DIM   512
#define IN_DIM  1024
#define OUT_DIM 1024

#define BM 64
#define BN 64
#define BK 16
#define NTHREADS 512
#define KSPLIT 2
#define K_PER_GROUP (IN_DIM / KSPLIT)       // 512
#define NTILES (K_PER_GROUP / BK)           // 32

// smem layout (floats):
//   group g base = g*4096
//   X tiles: [base + buf*1024 + k*64 + m]   (2 bufs x 16 x 64)
//   W tiles: [base + 2048 + buf*1024 + k*64 + n]
// epilogue partials reuse [0, 4096): P[m*64 + n]
#define SMEM_FLOATS 8192

__global__ __launch_bounds__(NTHREADS, 1)
void tropical_mm_kernel(const float* __restrict__ X,
                        const float* __restrict__ W,
                        float* __restrict__ Y) {
    __shared__ float sm[SMEM_FLOATS];

    const int tid  = threadIdx.x;
    const int g    = tid >> 8;          // k-group: 0 or 1
    const int gtid = tid & 255;
    const int tx   = gtid & 15;         // 0..15 over N
    const int ty   = gtid >> 4;         // 0..15 over M
    const int bm   = blockIdx.y * BM;
    const int bn   = blockIdx.x * BN;

    // Loader mapping within group: lr = row 0..63, lc = k offset {0,4,8,12}.
    const int lr = gtid & 63;
    const int lc = (gtid >> 6) << 2;

    const int kb = g * K_PER_GROUP;
    const float* Xg = X + (size_t)(bm + lr) * IN_DIM + kb + lc;
    const float* Wg = W + (size_t)(bn + lr) * IN_DIM + kb + lc;

    float* Xs = sm + g * 4096;          // [buf*1024 + k*64 + m]
    float* Ws = sm + g * 4096 + 2048;   // [buf*1024 + k*64 + n]

    const float NEG_INF = __int_as_float(0xff800000);
    float acc[4][4];
#pragma unroll
    for (int i = 0; i < 4; i++)
#pragma unroll
        for (int j = 0; j < 4; j++)
            acc[i][j] = NEG_INF;

    // ---- prologue: tile 0 -> buffer 0 ----
    float4 xv = *(const float4*)(Xg);
    float4 wv = *(const float4*)(Wg);
    Xs[(lc + 0) * 64 + lr] = xv.x;
    Xs[(lc + 1) * 64 + lr] = xv.y;
    Xs[(lc + 2) * 64 + lr] = xv.z;
    Xs[(lc + 3) * 64 + lr] = xv.w;
    Ws[(lc + 0) * 64 + lr] = wv.x;
    Ws[(lc + 1) * 64 + lr] = wv.y;
    Ws[(lc + 2) * 64 + lr] = wv.z;
    Ws[(lc + 3) * 64 + lr] = wv.w;
    __syncthreads();

    int buf = 0;
    for (int kt = 1; kt < NTILES; kt++) {
        xv = *(const float4*)(Xg + kt * BK);
        wv = *(const float4*)(Wg + kt * BK);

#pragma unroll
        for (int k = 0; k < BK; k++) {
            float4 a = *(const float4*)(&Xs[buf * 1024 + k * 64 + ty * 4]);
            float4 b = *(const float4*)(&Ws[buf * 1024 + k * 64 + tx * 4]);
            float xa0 = a.x, xa1 = a.y, xa2 = a.z, xa3 = a.w;
            float wb0 = b.x, wb1 = b.y, wb2 = b.z, wb3 = b.w;
            acc[0][0] = fmaxf(acc[0][0], xa0 + wb0);
            acc[0][1] = fmaxf(acc[0][1], xa0 + wb1);
            acc[0][2] = fmaxf(acc[0][2], xa0 + wb2);
            acc[0][3] = fmaxf(acc[0][3], xa0 + wb3);
            acc[1][0] = fmaxf(acc[1][0], xa1 + wb0);
            acc[1][1] = fmaxf(acc[1][1], xa1 + wb1);
            acc[1][2] = fmaxf(acc[1][2], xa1 + wb2);
            acc[1][3] = fmaxf(acc[1][3], xa1 + wb3);
            acc[2][0] = fmaxf(acc[2][0], xa2 + wb0);
            acc[2][1] = fmaxf(acc[2][1], xa2 + wb1);
            acc[2][2] = fmaxf(acc[2][2], xa2 + wb2);
            acc[2][3] = fmaxf(acc[2][3], xa2 + wb3);
            acc[3][0] = fmaxf(acc[3][0], xa3 + wb0);
            acc[3][1] = fmaxf(acc[3][1], xa3 + wb1);
            acc[3][2] = fmaxf(acc[3][2], xa3 + wb2);
            acc[3][3] = fmaxf(acc[3][3], xa3 + wb3);
        }

        buf ^= 1;
        Xs[buf * 1024 + (lc + 0) * 64 + lr] = xv.x;
        Xs[buf * 1024 + (lc + 1) * 64 + lr] = xv.y;
        Xs[buf * 1024 + (lc + 2) * 64 + lr] = xv.z;
        Xs[buf * 1024 + (lc + 3) * 64 + lr] = xv.w;
        Ws[buf * 1024 + (lc + 0) * 64 + lr] = wv.x;
        Ws[buf * 1024 + (lc + 1) * 64 + lr] = wv.y;
        Ws[buf * 1024 + (lc + 2) * 64 + lr] = wv.z;
        Ws[buf * 1024 + (lc + 3) * 64 + lr] = wv.w;
        __syncthreads();
    }

    // ---- final tile ----
#pragma unroll
    for (int k = 0; k < BK; k++) {
        float4 a = *(const float4*)(&Xs[buf * 1024 + k * 64 + ty * 4]);
        float4 b = *(const float4*)(&Ws[buf * 1024 + k * 64 + tx * 4]);
        float xa0 = a.x, xa1 = a.y, xa2 = a.z, xa3 = a.w;
        float wb0 = b.x, wb1 = b.y, wb2 = b.z, wb3 = b.w;
        acc[0][0] = fmaxf(acc[0][0], xa0 + wb0);
        acc[0][1] = fmaxf(acc[0][1], xa0 + wb1);
        acc[0][2] = fmaxf(acc[0][2], xa0 + wb2);
        acc[0][3] = fmaxf(acc[0][3], xa0 + wb3);
        acc[1][0] = fmaxf(acc[1][0], xa1 + wb0);
        acc[1][1] = fmaxf(acc[1][1], xa1 + wb1);
        acc[1][2] = fmaxf(acc[1][2], xa1 + wb2);
        acc[1][3] = fmaxf(acc[1][3], xa1 + wb3);
        acc[2][0] = fmaxf(acc[2][0], xa2 + wb0);
        acc[2][1] = fmaxf(acc[2][1], xa2 + wb1);
        acc[2][2] = fmaxf(acc[2][2], xa2 + wb2);
        acc[2][3] = fmaxf(acc[2][3], xa2 + wb3);
        acc[3][0] = fmaxf(acc[3][0], xa3 + wb0);
        acc[3][1] = fmaxf(acc[3][1], xa3 + wb1);
        acc[3][2] = fmaxf(acc[3][2], xa3 + wb2);
        acc[3][3] = fmaxf(acc[3][3], xa3 + wb3);
    }

    // ---- split-K combine: tiles are dead after this sync ----
    __syncthreads();

    if (g == 1) {
        // group 1 writes its partials P[m*64 + n] into sm[0, 4096)
#pragma unroll
        for (int i = 0; i < 4; i++) {
            float4 o;
            o.x = acc[i][0];
            o.y = acc[i][1];
            o.z = acc[i][2];
            o.w = acc[i][3];
            *(float4*)(&sm[(ty * 4 + i) * 64 + tx * 4]) = o;
        }
    }
    __syncthreads();

    if (g == 0) {
#pragma unroll
        for (int i = 0; i < 4; i++) {
            float4 p = *(const float4*)(&sm[(ty * 4 + i) * 64 + tx * 4]);
            float4 o;
            o.x = fmaxf(acc[i][0], p.x);
            o.y = fmaxf(acc[i][1], p.y);
            o.z = fmaxf(acc[i][2], p.z);
            o.w = fmaxf(acc[i][3], p.w);
            *(float4*)(&Y[(size_t)(bm + ty * 4 + i) * OUT_DIM + bn + tx * 4]) = o;
        }
    }
}

extern "C" void kernel_launch(void* const* d_in, const int* in_sizes, int n_in,
                              void* d_out, int out_size) {
    // X: 512*1024 elems, W: 1024*1024 elems.
    const float* X;
    const float* W;
    if (in_sizes[0] == B_DIM * IN_DIM) {
        X = (const float*)d_in[0];
        W = (const float*)d_in[1];
    } else {
        X = (const float*)d_in[1];
        W = (const float*)d_in[0];
    }
    float* Y = (float*)d_out;

    dim3 grid(OUT_DIM / BN, B_DIM / BM);  // 16 x 8 = 128 blocks
    dim3 block(NTHREADS);
    tropical_mm_kernel<<<grid, block>>>(X, W, Y);
}

// round 6
// speedup vs baseline: 2.3784x; 2.1772x over previous
#include <cuda_runtime.h>
#include <cuda_bf16.h>

// Tropical (max-plus) matmul: Y[b, j] = max_i (X[b, i] + W[j, i])
// B=512, IN=1024, OUT=1024, fp32.
//
// Algorithmic rewrite (exact): W is tiny (0.02*N(0,1)), so per row b only
// indices i with X[b,i] + Whi_i >= max_i(X[b,i] + Wlo_i) can ever be the
// argmax for ANY j (Wlo/Whi = per-column min/max of W). For Gaussian X this
// candidate set has ~1-3 entries -> work drops from 5.4e8 ops to ~1e6.
// Pruning is conservative: correct for all inputs; perf is input-adaptive.
//
// Pipeline (stream-ordered, graph-capturable, no allocations):
//   k_transpose: W[j][i] -> WT[i][j]        (coalesced candidate rows later)
//   k_minmax:    Wlo_i, Whi_i from WT rows
//   k_cand:      per-row m_b + ballot-compacted candidate list
//   k_out:       Y[b,j] = max_c (x_c + WT[i_c][j])

#define B_DIM   512
#define IN_DIM  1024
#define OUT_DIM 1024

// ---- scratch (device globals; no dynamic allocation) ----
__device__ float g_WT[(size_t)IN_DIM * OUT_DIM];   // 4 MB: WT[i][j] = W[j][i]
__device__ float g_Wlo[IN_DIM];
__device__ float g_Whi[IN_DIM];
__device__ float g_cx[(size_t)B_DIM * IN_DIM];     // candidate X values (2 MB)
__device__ int   g_ci[(size_t)B_DIM * IN_DIM];     // candidate indices  (2 MB)
__device__ int   g_cn[B_DIM];                      // candidate counts

#define NEG_INF __int_as_float(0xff800000)

// ---- 1) transpose W (row-major [OUT][IN]) into WT [IN][OUT] ----
__global__ __launch_bounds__(256)
void k_transpose(const float* __restrict__ W) {
    __shared__ float s[32][33];
    const int bx = blockIdx.x;   // i-tile
    const int by = blockIdx.y;   // j-tile
    const int tx = threadIdx.x;  // 0..31
    const int ty = threadIdx.y;  // 0..7

    // s[a][b] = W[by*32 + a][bx*32 + b]  (coalesced loads over b=tx)
#pragma unroll
    for (int y = ty; y < 32; y += 8)
        s[y][tx] = W[(size_t)(by * 32 + y) * IN_DIM + bx * 32 + tx];
    __syncthreads();

    // WT[bx*32 + y][by*32 + tx] = W[by*32 + tx][bx*32 + y] = s[tx][y]
#pragma unroll
    for (int y = ty; y < 32; y += 8)
        g_WT[(size_t)(bx * 32 + y) * OUT_DIM + by * 32 + tx] = s[tx][y];
}

// ---- 2) per-column (over j) min/max of W == per-row min/max of WT ----
__global__ __launch_bounds__(256)
void k_minmax() {
    const int w    = threadIdx.x >> 5;
    const int lane = threadIdx.x & 31;
    const int i    = blockIdx.x * 8 + w;      // grid 128 * 8 warps = 1024 rows

    const float* row = g_WT + (size_t)i * OUT_DIM;
    float lo = row[lane];
    float hi = lo;
#pragma unroll 8
    for (int t = 1; t < 32; t++) {
        float v = row[lane + 32 * t];
        lo = fminf(lo, v);
        hi = fmaxf(hi, v);
    }
#pragma unroll
    for (int o = 16; o; o >>= 1) {
        lo = fminf(lo, __shfl_xor_sync(0xffffffffu, lo, o));
        hi = fmaxf(hi, __shfl_xor_sync(0xffffffffu, hi, o));
    }
    if (lane == 0) {
        g_Wlo[i] = lo;
        g_Whi[i] = hi;
    }
}

// ---- 3) per-row candidate extraction (warp per row) ----
__global__ __launch_bounds__(256)
void k_cand(const float* __restrict__ X) {
    const int w    = threadIdx.x >> 5;
    const int lane = threadIdx.x & 31;
    const int b    = blockIdx.x * 8 + w;      // grid 64 * 8 warps = 512 rows

    const float* xr = X + (size_t)b * IN_DIM;

    // m_b = max_i (X[b,i] + Wlo_i)  — lower bound on every output M_j
    float m = NEG_INF;
#pragma unroll 8
    for (int t = 0; t < 32; t++) {
        int i = t * 32 + lane;
        m = fmaxf(m, xr[i] + g_Wlo[i]);
    }
#pragma unroll
    for (int o = 16; o; o >>= 1)
        m = fmaxf(m, __shfl_xor_sync(0xffffffffu, m, o));

    // keep i iff X[b,i] + Whi_i >= m_b (it could win for some j)
    int base = 0;
    const unsigned lmask = (1u << lane) - 1u;
#pragma unroll 4
    for (int t = 0; t < 32; t++) {
        int i = t * 32 + lane;
        float v = xr[i];
        bool f = (v + g_Whi[i] >= m);
        unsigned bal = __ballot_sync(0xffffffffu, f);
        if (f) {
            int pos = base + __popc(bal & lmask);
            g_cx[(size_t)b * IN_DIM + pos] = v;
            g_ci[(size_t)b * IN_DIM + pos] = i;
        }
        base += __popc(bal);
    }
    if (lane == 0) g_cn[b] = base;   // >= 1 always (argmax survives)
}

// ---- 4) output: Y[b,j] = max over candidates (x_c + WT[i_c][j]) ----
__global__ __launch_bounds__(256)
void k_out(float* __restrict__ Y) {
    __shared__ float scx[IN_DIM];
    __shared__ int   sci[IN_DIM];

    const int b   = blockIdx.x;               // grid 512
    const int tid = threadIdx.x;

    const int n = g_cn[b];
    for (int c = tid; c < n; c += 256) {
        scx[c] = g_cx[(size_t)b * IN_DIM + c];
        sci[c] = g_ci[(size_t)b * IN_DIM + c];
    }
    __syncthreads();

    float a0 = NEG_INF, a1 = NEG_INF, a2 = NEG_INF, a3 = NEG_INF;
    for (int c = 0; c < n; c++) {
        float xc = scx[c];                    // smem broadcast
        const float* wr = g_WT + (size_t)sci[c] * OUT_DIM;
        a0 = fmaxf(a0, xc + wr[tid]);
        a1 = fmaxf(a1, xc + wr[tid + 256]);
        a2 = fmaxf(a2, xc + wr[tid + 512]);
        a3 = fmaxf(a3, xc + wr[tid + 768]);
    }
    float* yr = Y + (size_t)b * OUT_DIM;
    yr[tid]       = a0;
    yr[tid + 256] = a1;
    yr[tid + 512] = a2;
    yr[tid + 768] = a3;
}

extern "C" void kernel_launch(void* const* d_in, const int* in_sizes, int n_in,
                              void* d_out, int out_size) {
    // X: 512*1024 elems, W: 1024*1024 elems.
    const float* X;
    const float* W;
    if (in_sizes[0] == B_DIM * IN_DIM) {
        X = (const float*)d_in[0];
        W = (const float*)d_in[1];
    } else {
        X = (const float*)d_in[1];
        W = (const float*)d_in[0];
    }
    float* Y = (float*)d_out;

    k_transpose<<<dim3(IN_DIM / 32, OUT_DIM / 32), dim3(32, 8)>>>(W);
    k_minmax<<<IN_DIM / 8, 256>>>();
    k_cand<<<B_DIM / 8, 256>>>(X);
    k_out<<<B_DIM, 256>>>(Y);
}

// round 7
// speedup vs baseline: 4.0531x; 1.7041x over previous
#include <cuda_runtime.h>
#include <cuda_bf16.h>

// Tropical (max-plus) matmul: Y[b, j] = max_i (X[b, i] + W[j, i])
// B=512, IN=1024, OUT=1024, fp32.
//
// Exact candidate pruning (R3 idea) collapsed to TWO kernels, no transpose:
//   k_minmax: per-column min/max of W (coalesced reads) merged via
//             order-preserving-uint atomicMax into zero-initialized globals
//             (idempotent across graph replays -> deterministic).
//   k_fused:  per row b: m_b = max_i(X+Wlo); candidates {i : X+Whi >= m_b}
//             (smem atomicAdd compaction — order-free, max is commutative);
//             Y[b,j] = max_c (x_c + W[j][i_c]) reading W columns in place
//             (sector-wasteful but tiny at n~2 candidates; W is L2-resident).

#define B_DIM   512
#define IN_DIM  1024
#define OUT_DIM 1024

#define NEG_INF __int_as_float(0xff800000)

// Zero-initialized at module load. enc() maps float order to uint order with
// enc(f) > 0 for all finite f, so 0 is a neutral element for atomicMax.
// Replays re-run atomicMax over identical data: idempotent, same final value.
__device__ unsigned g_WhiK[IN_DIM];   // max over j of enc(W[j][i])
__device__ unsigned g_WloK[IN_DIM];   // max over j of ~enc(W[j][i])  (== min)

__device__ __forceinline__ unsigned enc_f(float f) {
    unsigned u = __float_as_uint(f);
    return (u & 0x80000000u) ? ~u : (u | 0x80000000u);
}
__device__ __forceinline__ float dec_f(unsigned e) {
    return (e & 0x80000000u) ? __uint_as_float(e & 0x7fffffffu)
                             : __uint_as_float(~e);
}

// ---- 1) per-column (over j) min/max of W, coalesced ----
// grid (IN/256, 32): block handles 256 columns x 32 rows; 128 blocks.
__global__ __launch_bounds__(256)
void k_minmax(const float* __restrict__ W) {
    const int c  = blockIdx.x * 256 + threadIdx.x;   // column i
    const int r0 = blockIdx.y * 32;                  // row chunk base

    const float* p = W + (size_t)r0 * IN_DIM + c;
    float lo = p[0];
    float hi = lo;
#pragma unroll 8
    for (int r = 1; r < 32; r++) {
        float v = p[(size_t)r * IN_DIM];
        lo = fminf(lo, v);
        hi = fmaxf(hi, v);
    }
    atomicMax(&g_WhiK[c], enc_f(hi));
    atomicMax(&g_WloK[c], ~enc_f(lo));
}

// ---- 2) fused candidate extraction + output (block per row b) ----
__global__ __launch_bounds__(256)
void k_fused(const float* __restrict__ X,
             const float* __restrict__ W,
             float* __restrict__ Y) {
    __shared__ float s_red[8];
    __shared__ float s_m;
    __shared__ int   s_n;
    __shared__ float scx[IN_DIM];
    __shared__ int   sci[IN_DIM];

    const int b    = blockIdx.x;
    const int tid  = threadIdx.x;
    const int lane = tid & 31;
    const int wid  = tid >> 5;

    if (tid == 0) s_n = 0;

    // load 4 consecutive i per thread
    const float4 xv = *(const float4*)(X + (size_t)b * IN_DIM + tid * 4);
    float wlo0 = dec_f(~g_WloK[tid * 4 + 0]);
    float wlo1 = dec_f(~g_WloK[tid * 4 + 1]);
    float wlo2 = dec_f(~g_WloK[tid * 4 + 2]);
    float wlo3 = dec_f(~g_WloK[tid * 4 + 3]);

    // m_b = max_i (X[b,i] + Wlo_i)
    float m = fmaxf(fmaxf(xv.x + wlo0, xv.y + wlo1),
                    fmaxf(xv.z + wlo2, xv.w + wlo3));
#pragma unroll
    for (int o = 16; o; o >>= 1)
        m = fmaxf(m, __shfl_xor_sync(0xffffffffu, m, o));
    if (lane == 0) s_red[wid] = m;
    __syncthreads();
    if (wid == 0) {
        float t = (lane < 8) ? s_red[lane] : NEG_INF;
#pragma unroll
        for (int o = 4; o; o >>= 1)
            t = fmaxf(t, __shfl_xor_sync(0xffffffffu, t, o));
        if (lane == 0) s_m = t;
    }
    __syncthreads();
    m = s_m;

    // candidates: i with X[b,i] + Whi_i >= m  (order in list is irrelevant:
    // final result is a max over the set, exactly commutative)
    float whi0 = dec_f(g_WhiK[tid * 4 + 0]);
    float whi1 = dec_f(g_WhiK[tid * 4 + 1]);
    float whi2 = dec_f(g_WhiK[tid * 4 + 2]);
    float whi3 = dec_f(g_WhiK[tid * 4 + 3]);
    if (xv.x + whi0 >= m) { int p = atomicAdd(&s_n, 1); scx[p] = xv.x; sci[p] = tid * 4 + 0; }
    if (xv.y + whi1 >= m) { int p = atomicAdd(&s_n, 1); scx[p] = xv.y; sci[p] = tid * 4 + 1; }
    if (xv.z + whi2 >= m) { int p = atomicAdd(&s_n, 1); scx[p] = xv.z; sci[p] = tid * 4 + 2; }
    if (xv.w + whi3 >= m) { int p = atomicAdd(&s_n, 1); scx[p] = xv.w; sci[p] = tid * 4 + 3; }
    __syncthreads();

    const int n = s_n;   // >= 1 always (the argmax of m survives)

    // Y[b, j] = max_c (x_c + W[j][i_c]); thread covers j = tid*4 .. tid*4+3
    float a0 = NEG_INF, a1 = NEG_INF, a2 = NEG_INF, a3 = NEG_INF;
    for (int c = 0; c < n; c++) {
        const float xc = scx[c];
        const float* wc = W + sci[c];
        a0 = fmaxf(a0, xc + wc[(size_t)(tid * 4 + 0) * IN_DIM]);
        a1 = fmaxf(a1, xc + wc[(size_t)(tid * 4 + 1) * IN_DIM]);
        a2 = fmaxf(a2, xc + wc[(size_t)(tid * 4 + 2) * IN_DIM]);
        a3 = fmaxf(a3, xc + wc[(size_t)(tid * 4 + 3) * IN_DIM]);
    }
    float4 o4;
    o4.x = a0; o4.y = a1; o4.z = a2; o4.w = a3;
    *(float4*)(Y + (size_t)b * OUT_DIM + tid * 4) = o4;
}

extern "C" void kernel_launch(void* const* d_in, const int* in_sizes, int n_in,
                              void* d_out, int out_size) {
    // X: 512*1024 elems, W: 1024*1024 elems.
    const float* X;
    const float* W;
    if (in_sizes[0] == B_DIM * IN_DIM) {
        X = (const float*)d_in[0];
        W = (const float*)d_in[1];
    } else {
        X = (const float*)d_in[1];
        W = (const float*)d_in[0];
    }
    float* Y = (float*)d_out;

    k_minmax<<<dim3(IN_DIM / 256, 32), 256>>>(W);
    k_fused<<<B_DIM, 256>>>(X, W, Y);
}

// round 9
// speedup vs baseline: 5.7901x; 1.4286x over previous
#include <cuda_runtime.h>
#include <cuda_bf16.h>

// Tropical (max-plus) matmul: Y[b, j] = max_i (X[b, i] + W[j, i])
// B=512, IN=1024, OUT=1024, fp32.
//
// Exact candidate pruning, two kernels:
//   k_prep:  fused transpose (W -> WT, both sides coalesced via smem tile)
//            + per-column min/max computed from the SAME resident tile,
//            merged with order-preserving-uint atomicMax (idempotent across
//            graph replays -> deterministic).
//   k_fused: per row b: m_b = max_i(X+Wlo); candidates {i : X+Whi >= m_b};
//            Y[b,j] = max_c (x_c + WT[i_c][j]) with COALESCED float4 reads
//            of WT rows (fixes R7's 32-wavefront-per-LDG column gather).

#define B_DIM   512
#define IN_DIM  1024
#define OUT_DIM 1024

#define NEG_INF __int_as_float(0xff800000)

// ---- scratch (device globals; zero-init; no dynamic allocation) ----
__device__ float    g_WT[(size_t)IN_DIM * OUT_DIM];   // 4 MB: WT[i][j] = W[j][i]
__device__ unsigned g_WhiK[IN_DIM];   // max over j of enc(W[j][i])
__device__ unsigned g_WloK[IN_DIM];   // max over j of ~enc(W[j][i]) (== min)

// Order-preserving float->uint: enc(f) strictly increasing, enc(f) > 0 for
// all finite f, so 0 (static init) is neutral for atomicMax. Replays redo
// identical atomicMax ops: idempotent.
__device__ __forceinline__ unsigned enc_f(float f) {
    unsigned u = __float_as_uint(f);
    return (u & 0x80000000u) ? ~u : (u | 0x80000000u);
}
__device__ __forceinline__ float dec_f(unsigned e) {
    return (e & 0x80000000u) ? __uint_as_float(e & 0x7fffffffu)
                             : __uint_as_float(~e);
}

// ---- 1) fused transpose + per-column min/max ----
// grid (IN/32, OUT/32) = 32x32 blocks, block (32, 8).
__global__ __launch_bounds__(256)
void k_prep(const float* __restrict__ W) {
    __shared__ float s[32][33];
    __shared__ float red_lo[8][32];
    __shared__ float red_hi[8][32];

    const int bx = blockIdx.x;   // i-tile
    const int by = blockIdx.y;   // j-tile
    const int tx = threadIdx.x;  // 0..31
    const int ty = threadIdx.y;  // 0..7

    // load tile: s[a][b] = W[by*32+a][bx*32+b], coalesced over b=tx
#pragma unroll
    for (int y = ty; y < 32; y += 8)
        s[y][tx] = W[(size_t)(by * 32 + y) * IN_DIM + bx * 32 + tx];
    __syncthreads();

    // transposed write: WT[bx*32+y][by*32+tx] = s[tx][y], coalesced over tx
#pragma unroll
    for (int y = ty; y < 32; y += 8)
        g_WT[(size_t)(bx * 32 + y) * OUT_DIM + by * 32 + tx] = s[tx][y];

    // per-column (i = bx*32+tx) min/max over the 32 j's of this tile.
    // thread (tx,ty) reduces rows a = ty, ty+8, ty+16, ty+24 of column tx;
    // s[a][tx] with stride-33 rows -> conflict-free within a warp.
    float lo = s[ty][tx];
    float hi = lo;
#pragma unroll
    for (int k = 1; k < 4; k++) {
        float v = s[ty + 8 * k][tx];
        lo = fminf(lo, v);
        hi = fmaxf(hi, v);
    }
    red_lo[ty][tx] = lo;
    red_hi[ty][tx] = hi;
    __syncthreads();

    if (ty == 0) {
#pragma unroll
        for (int r = 1; r < 8; r++) {
            lo = fminf(lo, red_lo[r][tx]);
            hi = fmaxf(hi, red_hi[r][tx]);
        }
        atomicMax(&g_WhiK[bx * 32 + tx], enc_f(hi));
        atomicMax(&g_WloK[bx * 32 + tx], ~enc_f(lo));
    }
}

// ---- 2) fused candidate extraction + output (block per row b) ----
__global__ __launch_bounds__(256)
void k_fused(const float* __restrict__ X,
             float* __restrict__ Y) {
    __shared__ float s_red[8];
    __shared__ float s_m;
    __shared__ int   s_n;
    __shared__ float scx[IN_DIM];
    __shared__ int   sci[IN_DIM];

    const int b    = blockIdx.x;
    const int tid  = threadIdx.x;
    const int lane = tid & 31;
    const int wid  = tid >> 5;

    if (tid == 0) s_n = 0;

    // 4 consecutive i per thread
    const float4 xv = *(const float4*)(X + (size_t)b * IN_DIM + tid * 4);
    float wlo0 = dec_f(~g_WloK[tid * 4 + 0]);
    float wlo1 = dec_f(~g_WloK[tid * 4 + 1]);
    float wlo2 = dec_f(~g_WloK[tid * 4 + 2]);
    float wlo3 = dec_f(~g_WloK[tid * 4 + 3]);

    // m_b = max_i (X[b,i] + Wlo_i)
    float m = fmaxf(fmaxf(xv.x + wlo0, xv.y + wlo1),
                    fmaxf(xv.z + wlo2, xv.w + wlo3));
#pragma unroll
    for (int o = 16; o; o >>= 1)
        m = fmaxf(m, __shfl_xor_sync(0xffffffffu, m, o));
    if (lane == 0) s_red[wid] = m;
    __syncthreads();
    if (wid == 0) {
        float t = (lane < 8) ? s_red[lane] : NEG_INF;
#pragma unroll
        for (int o = 4; o; o >>= 1)
            t = fmaxf(t, __shfl_xor_sync(0xffffffffu, t, o));
        if (lane == 0) s_m = t;
    }
    __syncthreads();
    m = s_m;

    // candidates: i with X[b,i] + Whi_i >= m (list order irrelevant: result
    // is a commutative max over the set)
    float whi0 = dec_f(g_WhiK[tid * 4 + 0]);
    float whi1 = dec_f(g_WhiK[tid * 4 + 1]);
    float whi2 = dec_f(g_WhiK[tid * 4 + 2]);
    float whi3 = dec_f(g_WhiK[tid * 4 + 3]);
    if (xv.x + whi0 >= m) { int p = atomicAdd(&s_n, 1); scx[p] = xv.x; sci[p] = tid * 4 + 0; }
    if (xv.y + whi1 >= m) { int p = atomicAdd(&s_n, 1); scx[p] = xv.y; sci[p] = tid * 4 + 1; }
    if (xv.z + whi2 >= m) { int p = atomicAdd(&s_n, 1); scx[p] = xv.z; sci[p] = tid * 4 + 2; }
    if (xv.w + whi3 >= m) { int p = atomicAdd(&s_n, 1); scx[p] = xv.w; sci[p] = tid * 4 + 3; }
    __syncthreads();

    const int n = s_n;   // >= 1 always (the argmax of m survives)

    // Y[b,j] = max_c (x_c + WT[i_c][j]); coalesced float4 per candidate row
    float a0 = NEG_INF, a1 = NEG_INF, a2 = NEG_INF, a3 = NEG_INF;
    for (int c = 0; c < n; c++) {
        const float xc = scx[c];
        const float4 wv = *(const float4*)(g_WT + (size_t)sci[c] * OUT_DIM + tid * 4);
        a0 = fmaxf(a0, xc + wv.x);
        a1 = fmaxf(a1, xc + wv.y);
        a2 = fmaxf(a2, xc + wv.z);
        a3 = fmaxf(a3, xc + wv.w);
    }
    float4 o4;
    o4.x = a0; o4.y = a1; o4.z = a2; o4.w = a3;
    *(float4*)(Y + (size_t)b * OUT_DIM + tid * 4) = o4;
}

extern "C" void kernel_launch(void* const* d_in, const int* in_sizes, int n_in,
                              void* d_out, int out_size) {
    // X: 512*1024 elems, W: 1024*1024 elems.
    const float* X;
    const float* W;
    if (in_sizes[0] == B_DIM * IN_DIM) {
        X = (const float*)d_in[0];
        W = (const float*)d_in[1];
    } else {
        X = (const float*)d_in[1];
        W = (const float*)d_in[0];
    }
    float* Y = (float*)d_out;

    k_prep<<<dim3(IN_DIM / 32, OUT_DIM / 32), dim3(32, 8)>>>(W);
    k_fused<<<B_DIM, 256>>>(X, Y);
}

// round 15
// speedup vs baseline: 5.9107x; 1.0208x over previous
#include <cuda_runtime.h>
#include <cuda_bf16.h>

// Tropical (max-plus) matmul: Y[b, j] = max_i (X[b, i] + W[j, i])
// B=512, IN=1024, OUT=1024, fp32.
//
// Exact candidate pruning, two kernels:
//   k_prep:  fused transpose (W -> WT) + per-column min/max (unchanged R7).
//   k_fused: WARP-PER-ROW rewrite. One warp owns row b: lane-local X chunk
//            (8 float4), m_b via 5 shfls (no block barriers), per-warp smem
//            candidate list (order-free, max commutative), coalesced WT-row
//            gather + store. Grid 128x4warps = 512 warps < 1 wave.

#define B_DIM   512
#define IN_DIM  1024
#define OUT_DIM 1024

#define NEG_INF __int_as_float(0xff800000)

// ---- scratch (device globals; zero-init; no dynamic allocation) ----
__device__ float    g_WT[(size_t)IN_DIM * OUT_DIM];   // 4 MB: WT[i][j] = W[j][i]
__device__ unsigned g_WhiK[IN_DIM];   // max over j of enc(W[j][i])
__device__ unsigned g_WloK[IN_DIM];   // max over j of ~enc(W[j][i]) (== min)

// Order-preserving float->uint: enc strictly increasing, enc(f) > 0 for all
// finite f, so the zero static-init is neutral for atomicMax; replays redo
// identical atomicMax ops (idempotent -> deterministic).
__device__ __forceinline__ unsigned enc_f(float f) {
    unsigned u = __float_as_uint(f);
    return (u & 0x80000000u) ? ~u : (u | 0x80000000u);
}
__device__ __forceinline__ float dec_f(unsigned e) {
    return (e & 0x80000000u) ? __uint_as_float(e & 0x7fffffffu)
                             : __uint_as_float(~e);
}

// ---- 1) fused transpose + per-column min/max (unchanged from R7) ----
__global__ __launch_bounds__(256)
void k_prep(const float* __restrict__ W) {
    __shared__ float s[32][33];
    __shared__ float red_lo[8][32];
    __shared__ float red_hi[8][32];

    const int bx = blockIdx.x;   // i-tile
    const int by = blockIdx.y;   // j-tile
    const int tx = threadIdx.x;  // 0..31
    const int ty = threadIdx.y;  // 0..7

#pragma unroll
    for (int y = ty; y < 32; y += 8)
        s[y][tx] = W[(size_t)(by * 32 + y) * IN_DIM + bx * 32 + tx];
    __syncthreads();

#pragma unroll
    for (int y = ty; y < 32; y += 8)
        g_WT[(size_t)(bx * 32 + y) * OUT_DIM + by * 32 + tx] = s[tx][y];

    float lo = s[ty][tx];
    float hi = lo;
#pragma unroll
    for (int k = 1; k < 4; k++) {
        float v = s[ty + 8 * k][tx];
        lo = fminf(lo, v);
        hi = fmaxf(hi, v);
    }
    red_lo[ty][tx] = lo;
    red_hi[ty][tx] = hi;
    __syncthreads();

    if (ty == 0) {
#pragma unroll
        for (int r = 1; r < 8; r++) {
            lo = fminf(lo, red_lo[r][tx]);
            hi = fmaxf(hi, red_hi[r][tx]);
        }
        atomicMax(&g_WhiK[bx * 32 + tx], enc_f(hi));
        atomicMax(&g_WloK[bx * 32 + tx], ~enc_f(lo));
    }
}

// ---- 2) warp-per-row fused kernel ----
// block = 128 threads (4 warps, 4 rows), grid = 128 blocks -> 512 rows.
#define WARPS_PER_BLOCK 4

__global__ __launch_bounds__(128)
void k_fused(const float* __restrict__ X,
             float* __restrict__ Y) {
    // per-warp candidate lists; worst case (adversarial W) all 1024 survive.
    __shared__ float scx[WARPS_PER_BLOCK][IN_DIM];
    __shared__ int   sci[WARPS_PER_BLOCK][IN_DIM];
    __shared__ int   s_n[WARPS_PER_BLOCK];

    const int lane = threadIdx.x & 31;
    const int w    = threadIdx.x >> 5;
    const int b    = blockIdx.x * WARPS_PER_BLOCK + w;

    if (lane == 0) s_n[w] = 0;
    __syncwarp();

    // lane-local X chunk: 8 float4 = 32 values, indices (r*32+lane)*4 + e
    const float4* X4 = (const float4*)(X + (size_t)b * IN_DIM);
    float4 xv[8];
#pragma unroll
    for (int r = 0; r < 8; r++)
        xv[r] = X4[r * 32 + lane];

    // m_b = max_i (X + Wlo) : lane-local max then 5 shfls
    const uint4* Wlo4 = (const uint4*)g_WloK;
    float m = NEG_INF;
#pragma unroll
    for (int r = 0; r < 8; r++) {
        uint4 lk = Wlo4[r * 32 + lane];
        m = fmaxf(m, xv[r].x + dec_f(~lk.x));
        m = fmaxf(m, xv[r].y + dec_f(~lk.y));
        m = fmaxf(m, xv[r].z + dec_f(~lk.z));
        m = fmaxf(m, xv[r].w + dec_f(~lk.w));
    }
#pragma unroll
    for (int o = 16; o; o >>= 1)
        m = fmaxf(m, __shfl_xor_sync(0xffffffffu, m, o));

    // candidates: X + Whi >= m (per-warp smem list; set is order-independent
    // and the final reduction is an exact commutative max)
    const uint4* Whi4 = (const uint4*)g_WhiK;
#pragma unroll
    for (int r = 0; r < 8; r++) {
        uint4 hk = Whi4[r * 32 + lane];
        const int i0 = (r * 32 + lane) * 4;
        if (xv[r].x + dec_f(hk.x) >= m) { int p = atomicAdd(&s_n[w], 1); scx[w][p] = xv[r].x; sci[w][p] = i0 + 0; }
        if (xv[r].y + dec_f(hk.y) >= m) { int p = atomicAdd(&s_n[w], 1); scx[w][p] = xv[r].y; sci[w][p] = i0 + 1; }
        if (xv[r].z + dec_f(hk.z) >= m) { int p = atomicAdd(&s_n[w], 1); scx[w][p] = xv[r].z; sci[w][p] = i0 + 2; }
        if (xv[r].w + dec_f(hk.w) >= m) { int p = atomicAdd(&s_n[w], 1); scx[w][p] = xv[r].w; sci[w][p] = i0 + 3; }
    }
    __syncwarp();

    const int n = s_n[w];   // >= 1 always (argmax of m survives)

    // Y[b, j] = max_c (x_c + WT[i_c][j]); 8 coalesced float4 per lane
    float4 acc[8];
#pragma unroll
    for (int r = 0; r < 8; r++)
        acc[r] = make_float4(NEG_INF, NEG_INF, NEG_INF, NEG_INF);

    for (int c = 0; c < n; c++) {
        const float xc = scx[w][c];
        const float4* wt = (const float4*)(g_WT + (size_t)sci[w][c] * OUT_DIM);
#pragma unroll
        for (int r = 0; r < 8; r++) {
            float4 wv = wt[r * 32 + lane];
            acc[r].x = fmaxf(acc[r].x, xc + wv.x);
            acc[r].y = fmaxf(acc[r].y, xc + wv.y);
            acc[r].z = fmaxf(acc[r].z, xc + wv.z);
            acc[r].w = fmaxf(acc[r].w, xc + wv.w);
        }
    }

    float4* Y4 = (float4*)(Y + (size_t)b * OUT_DIM);
#pragma unroll
    for (int r = 0; r < 8; r++)
        Y4[r * 32 + lane] = acc[r];
}

extern "C" void kernel_launch(void* const* d_in, const int* in_sizes, int n_in,
                              void* d_out, int out_size) {
    // X: 512*1024 elems, W: 1024*1024 elems.
    const float* X;
    const float* W;
    if (in_sizes[0] == B_DIM * IN_DIM) {
        X = (const float*)d_in[0];
        W = (const float*)d_in[1];
    } else {
        X = (const float*)d_in[1];
        W = (const float*)d_in[0];
    }
    float* Y = (float*)d_out;

    k_prep<<<dim3(IN_DIM / 32, OUT_DIM / 32), dim3(32, 8)>>>(W);
    k_fused<<<B_DIM / WARPS_PER_BLOCK, 32 * WARPS_PER_BLOCK>>>(X, Y);
}